// round 2
// baseline (speedup 1.0000x reference)
#include <cuda_runtime.h>

#define NB   8
#define NH   32
#define NW   32
#define NC   32
#define KH   3
#define KW   3
#define HO   30
#define WO   30
#define NF   64
#define NK   288   // KH*KW*NC

// Exact prune threshold: max over filters of (max_k w - min_k w).
// Computed on-device every launch (deterministic), so pruning is EXACT
// for arbitrary inputs.
__device__ float g_T;

__global__ void trop_T_kernel(const float* __restrict__ w) {
    int f = threadIdx.x;  // 64 threads, one per filter
    float wmax = -1e30f, wmin = 1e30f;
#pragma unroll 4
    for (int k = 0; k < NK; k++) {
        float v = w[k * NF + f];
        wmax = fmaxf(wmax, v);
        wmin = fminf(wmin, v);
    }
    float r = wmax - wmin;
#pragma unroll
    for (int o = 16; o; o >>= 1)
        r = fmaxf(r, __shfl_xor_sync(0xffffffffu, r, o));
    __shared__ float sr[2];
    if ((f & 31) == 0) sr[f >> 5] = r;
    __syncthreads();
    if (f == 0) g_T = fmaxf(sr[0], sr[1]);
}

__global__ __launch_bounds__(128) void trop_main_kernel(
    const float* __restrict__ x, const float* __restrict__ w,
    const float* __restrict__ bias, float* __restrict__ out) {
    // One block per output position (b, ho, wo).
    int pos = blockIdx.x;
    int wo = pos % WO;
    int ho = (pos / WO) % HO;
    int b  = pos / (WO * HO);

    __shared__ float p[NK];
    __shared__ float s_wmax[4], s_wmin[4];
    __shared__ float s_maxp, s_minp;
    __shared__ int   s_nmax, s_nmin;
    __shared__ short s_cmax[NK], s_cmin[NK];
    __shared__ float s_rmax[NF], s_rmin[NF];

    int t = threadIdx.x;

    // Phase 1: load the 3x3x32 patch into smem, tracking local max/min.
    float lmax = -1e30f, lmin = 1e30f;
    for (int k = t; k < NK; k += 128) {
        int ij = k >> 5;        // 0..8 = i*3+j  (channel fastest, matches ref)
        int c  = k & 31;
        int i  = ij / 3;
        int j  = ij - i * 3;
        float v = x[(((b * NH + ho + i) * NW) + (wo + j)) * NC + c];
        p[k] = v;
        lmax = fmaxf(lmax, v);
        lmin = fminf(lmin, v);
    }

    // Phase 2: block-reduce patch max/min.
#pragma unroll
    for (int o = 16; o; o >>= 1) {
        lmax = fmaxf(lmax, __shfl_xor_sync(0xffffffffu, lmax, o));
        lmin = fminf(lmin, __shfl_xor_sync(0xffffffffu, lmin, o));
    }
    if ((t & 31) == 0) { s_wmax[t >> 5] = lmax; s_wmin[t >> 5] = lmin; }
    __syncthreads();
    if (t == 0) {
        s_maxp = fmaxf(fmaxf(s_wmax[0], s_wmax[1]), fmaxf(s_wmax[2], s_wmax[3]));
        s_minp = fminf(fminf(s_wmin[0], s_wmin[1]), fminf(s_wmin[2], s_wmin[3]));
        s_nmax = 0;
        s_nmin = 0;
    }
    __syncthreads();

    // Phase 3: exact candidate compaction. A k can only achieve the
    // per-filter max if p[k] >= max_p - T (sym. for min). Order of the
    // compacted list is scheduler-dependent but max/min over a set is
    // order-independent -> deterministic output.
    float T = g_T;
    float thmax = s_maxp - T;
    float thmin = s_minp + T;
    for (int k = t; k < NK; k += 128) {
        float v = p[k];
        if (v >= thmax) { int idx = atomicAdd(&s_nmax, 1); s_cmax[idx] = (short)k; }
        if (v <= thmin) { int idx = atomicAdd(&s_nmin, 1); s_cmin[idx] = (short)k; }
    }
    __syncthreads();

    // Phase 4: warps 0-1 do the max side (one filter per thread),
    // warps 2-3 do the min side.
    if (t < NF) {
        int n = s_nmax;
        float m = -1e30f;
#pragma unroll 1
        for (int a = 0; a < n; a++) {
            int k = s_cmax[a];
            m = fmaxf(m, p[k] + w[k * NF + t]);
        }
        s_rmax[t] = m;
    } else {
        int f = t - NF;
        int n = s_nmin;
        float m = 1e30f;
#pragma unroll 1
        for (int a = 0; a < n; a++) {
            int k = s_cmin[a];
            m = fminf(m, p[k] + w[k * NF + f]);
        }
        s_rmin[f] = m;
    }
    __syncthreads();

    // Phase 5: combine + bias, write out.
    if (t < NF) {
        out[pos * NF + t] = s_rmax[t] - s_rmin[t] + bias[t];
    }
}

extern "C" void kernel_launch(void* const* d_in, const int* in_sizes, int n_in,
                              void* d_out, int out_size) {
    (void)in_sizes; (void)n_in; (void)out_size;
    const float* x    = (const float*)d_in[0];
    const float* w    = (const float*)d_in[1];
    const float* bias = (const float*)d_in[2];
    float* out = (float*)d_out;

    trop_T_kernel<<<1, NF>>>(w);
    trop_main_kernel<<<NB * HO * WO, 128>>>(x, w, bias, out);
}

// round 3
// speedup vs baseline: 2.4405x; 2.4405x over previous
#include <cuda_runtime.h>

#define NB   8
#define NH   32
#define NW   32
#define NC   32
#define HO   30
#define WO   30
#define NF   64
#define NK   288   // 3*3*32

// Exact prune threshold: max over filters of (max_k w - min_k w).
__device__ float g_T;

// 1024 threads: 16 k-chunks x 64 filters. 18 fully-independent L2 loads per
// thread (high MLP), then smem reduce. ~1us instead of ~9us.
__global__ __launch_bounds__(1024) void trop_T_kernel(const float* __restrict__ w) {
    __shared__ float smax[16][64];
    __shared__ float smin[16][64];
    int t = threadIdx.x;
    int f = t & 63;
    int chunk = t >> 6;           // 0..15
    int k0 = chunk * 18;
    float wmax = -1e30f, wmin = 1e30f;
#pragma unroll
    for (int q = 0; q < 18; q++) {
        float v = w[(k0 + q) * NF + f];
        wmax = fmaxf(wmax, v);
        wmin = fminf(wmin, v);
    }
    smax[chunk][f] = wmax;
    smin[chunk][f] = wmin;
    __syncthreads();
    if (t < 32) {
        // one warp reduces both halves of the filter axis -> no cross-warp sync
        float a0 = -1e30f, b0 = 1e30f, a1 = -1e30f, b1 = 1e30f;
#pragma unroll
        for (int q = 0; q < 16; q++) {
            a0 = fmaxf(a0, smax[q][t]);      b0 = fminf(b0, smin[q][t]);
            a1 = fmaxf(a1, smax[q][t + 32]); b1 = fminf(b1, smin[q][t + 32]);
        }
        float r = fmaxf(a0 - b0, a1 - b1);
#pragma unroll
        for (int o = 16; o; o >>= 1)
            r = fmaxf(r, __shfl_xor_sync(0xffffffffu, r, o));
        if (t == 0) g_T = r;
    }
}

// Block = (b, ho, wgroup of 10 wo positions). 320 threads = 10 warps,
// one warp per output position. Lane = channel.
__global__ __launch_bounds__(320) void trop_main_kernel(
    const float* __restrict__ x, const float* __restrict__ w,
    const float* __restrict__ bias, float* __restrict__ out) {

    int bx = blockIdx.x;
    int wg = bx % 3;              // wo group: cols wg*10 .. wg*10+11 needed
    int ho = (bx / 3) % HO;
    int b  = bx / (3 * HO);

    // s[row][col*32+ch], 12 columns per row
    __shared__ float s[3][12 * NC];

    int t = threadIdx.x;

    // Phase 1: contiguous float4 load. Row segment in x is contiguous over
    // (col, ch): 12*32 = 384 floats = 96 float4 per row.
    if (t < 288) {
        int row = t / 96;
        int q   = t - row * 96;
        const float4* src = (const float4*)(x + ((b * NH + ho + row) * NW + wg * 10) * NC);
        ((float4*)s[row])[q] = src[q];
    }
    __syncthreads();

    int wp   = t >> 5;            // warp = position within group
    int lane = t & 31;            // channel
    int wo   = wg * 10 + wp;

    // Phase 2: each lane keeps its 9 window values in registers.
    float v[9];
    float mx = -1e30f, mn = 1e30f;
#pragma unroll
    for (int i = 0; i < 3; i++)
#pragma unroll
        for (int j = 0; j < 3; j++) {
            float val = s[i][(wp + j) * NC + lane];
            v[i * 3 + j] = val;
            mx = fmaxf(mx, val);
            mn = fminf(mn, val);
        }
#pragma unroll
    for (int o = 16; o; o >>= 1) {
        mx = fmaxf(mx, __shfl_xor_sync(0xffffffffu, mx, o));
        mn = fminf(mn, __shfl_xor_sync(0xffffffffu, mn, o));
    }

    // Phase 3: exact prune. Any k with p_k < max_p - T cannot achieve the
    // per-filter max for ANY filter (sym. for min). Ballot + bit-iterate;
    // max/min over the candidate set is order-independent -> deterministic.
    float T = g_T;
    float thmax = mx - T;
    float thmin = mn + T;

    float amax0 = -1e30f, amax1 = -1e30f;   // filters lane, lane+32
    float amin0 =  1e30f, amin1 =  1e30f;

#pragma unroll
    for (int cell = 0; cell < 9; cell++) {
        float val = v[cell];
        unsigned mmax = __ballot_sync(0xffffffffu, val >= thmax);
        unsigned mmin = __ballot_sync(0xffffffffu, val <= thmin);
        while (mmax) {
            int c = __ffs(mmax) - 1; mmax &= mmax - 1;
            float pv = __shfl_sync(0xffffffffu, val, c);
            const float* wr = w + (cell * 32 + c) * NF;
            amax0 = fmaxf(amax0, pv + wr[lane]);
            amax1 = fmaxf(amax1, pv + wr[lane + 32]);
        }
        while (mmin) {
            int c = __ffs(mmin) - 1; mmin &= mmin - 1;
            float pv = __shfl_sync(0xffffffffu, val, c);
            const float* wr = w + (cell * 32 + c) * NF;
            amin0 = fminf(amin0, pv + wr[lane]);
            amin1 = fminf(amin1, pv + wr[lane + 32]);
        }
    }

    // Phase 4: combine + bias, coalesced store.
    int pos = (b * HO + ho) * WO + wo;
    out[pos * NF + lane]      = amax0 - amin0 + bias[lane];
    out[pos * NF + lane + 32] = amax1 - amin1 + bias[lane + 32];
}

extern "C" void kernel_launch(void* const* d_in, const int* in_sizes, int n_in,
                              void* d_out, int out_size) {
    (void)in_sizes; (void)n_in; (void)out_size;
    const float* x    = (const float*)d_in[0];
    const float* w    = (const float*)d_in[1];
    const float* bias = (const float*)d_in[2];
    float* out = (float*)d_out;

    trop_T_kernel<<<1, 1024>>>(w);
    trop_main_kernel<<<NB * HO * 3, 320>>>(x, w, bias, out);
}